// round 3
// baseline (speedup 1.0000x reference)
#include <cuda_runtime.h>
#include <cuda_bf16.h>

// GINEdgeLayer: out = MLP2((1+eps)*H + segment_sum(MLP1([H[src], edge_attr]), dst))
//
// Pipeline (5 launches, all graph-capturable, no allocations):
//   0. init_agg:  agg[n,:] = (1+eps) * H[n,:]
//   1. gemm<GATHER,RELU>:   X1 = relu(concat(H[src], edge_attr) @ msg_W1 + msg_b1)   [E,256]
//   2. gemm<SCATTER>:       agg[dst[e]] += X1[e] @ msg_W2 + msg_b2   (atomicAdd)     [N,128]
//   3. gemm<RELU>:          hid = relu(agg @ self_W1 + self_b1)                      [N,256]
//   4. gemm<>:              out = hid @ self_W2 + self_b2                            [N,128]

static constexpr int N_NODES  = 20000;
static constexpr int N_EDGES  = 200000;
static constexpr int DIM      = 128;
static constexpr int EDGE_DIM = 64;
static constexpr int HID      = 256;

static constexpr int BM = 64;
static constexpr int BN = 64;
static constexpr int BK = 32;

// Scratch: __device__ globals (no runtime allocation allowed).
__device__ float g_X1 [(size_t)N_EDGES * HID];   // ~204.8 MB
__device__ float g_agg[(size_t)N_NODES * DIM];   //  ~10.2 MB
__device__ float g_hid[(size_t)N_NODES * HID];   //  ~20.5 MB

static inline int cdiv(int a, int b) { return (a + b - 1) / b; }

__global__ __launch_bounds__(256)
void init_agg_kernel(const float* __restrict__ H, const float* __restrict__ eps) {
    int i = blockIdx.x * 256 + threadIdx.x;
    if (i < N_NODES * DIM) {
        g_agg[i] = (1.0f + eps[0]) * H[i];
    }
}

// Tiled SGEMM: C[M,Nout] = op(A[M,K] @ B[K,Nout] + bias)
//   GATHER:  A row m is concat(H[src[m], 0:128], edge_attr[m, 0:64]) (K must be 192)
//   RELU:    apply relu in epilogue
//   SCATTER: instead of storing C[m], atomicAdd into C[rowIdx[m]] (bias included per row)
// BM=64, BN=64, BK=32, 256 threads, 4x4 micro-tile per thread.
template<bool GATHER, bool RELU, bool SCATTER>
__global__ __launch_bounds__(256)
void gemm_kernel(const float* __restrict__ A,
                 const float* __restrict__ Hsrc,
                 const float* __restrict__ EA,
                 const int*   __restrict__ src,
                 const int*   __restrict__ dst,
                 const float* __restrict__ B,
                 const float* __restrict__ bias,
                 float*       __restrict__ C,
                 int M, int K, int Nout)
{
    __shared__ float As[BK][BM + 1];   // +1 pad: conflict-free transposed stores
    __shared__ float Bs[BK][BN];
    __shared__ int   rowIdx[BM];       // src (gather) or dst (scatter) indices

    const int tid = threadIdx.x;
    const int m0  = blockIdx.x * BM;
    const int n0  = blockIdx.y * BN;
    const int ty  = tid >> 4;          // 0..15 -> rows ty*4 .. ty*4+3
    const int tx  = tid & 15;          // 0..15 -> cols tx*4 .. tx*4+3

    if (GATHER)  { if (tid < BM) rowIdx[tid] = src[m0 + tid]; }
    if (SCATTER) { if (tid < BM) rowIdx[tid] = dst[m0 + tid]; }

    float acc[4][4];
#pragma unroll
    for (int i = 0; i < 4; i++)
#pragma unroll
        for (int j = 0; j < 4; j++) acc[i][j] = 0.0f;

    for (int k0 = 0; k0 < K; k0 += BK) {
        __syncthreads();   // also covers rowIdx fill before first A load

        // ---- Load A tile (BM x BK), stored transposed As[k][m] ----
        // idx = tid + t*256; r = idx/32 (row), c = idx%32 (k). Warp reads 32
        // consecutive k of one row: 128B coalesced. Store stride BM+1=65:
        // conflict-free STS.
#pragma unroll
        for (int t = 0; t < (BM * BK) / 256; t++) {
            int idx = tid + t * 256;
            int r = idx >> 5;
            int c = idx & 31;
            int gm = m0 + r;
            int gk = k0 + c;
            float v;
            if (GATHER) {
                // BK=32 tiles never straddle the 128 boundary (128 % 32 == 0)
                v = (gk < DIM) ? Hsrc[(size_t)rowIdx[r] * DIM + gk]
                               : EA[(size_t)gm * EDGE_DIM + (gk - DIM)];
            } else {
                v = (gm < M) ? A[(size_t)gm * K + gk] : 0.0f;
            }
            As[c][r] = v;
        }

        // ---- Load B tile (BK x BN) ----
#pragma unroll
        for (int t = 0; t < (BK * BN) / 256; t++) {
            int idx = tid + t * 256;
            int r = idx >> 6;
            int c = idx & 63;
            Bs[r][c] = B[(size_t)(k0 + r) * Nout + n0 + c];
        }

        __syncthreads();

        // ---- Compute ----
#pragma unroll
        for (int k = 0; k < BK; k++) {
            float a0 = As[k][ty * 4 + 0];
            float a1 = As[k][ty * 4 + 1];
            float a2 = As[k][ty * 4 + 2];
            float a3 = As[k][ty * 4 + 3];
            float4 b = *reinterpret_cast<const float4*>(&Bs[k][tx * 4]);
            acc[0][0] += a0 * b.x; acc[0][1] += a0 * b.y; acc[0][2] += a0 * b.z; acc[0][3] += a0 * b.w;
            acc[1][0] += a1 * b.x; acc[1][1] += a1 * b.y; acc[1][2] += a1 * b.z; acc[1][3] += a1 * b.w;
            acc[2][0] += a2 * b.x; acc[2][1] += a2 * b.y; acc[2][2] += a2 * b.z; acc[2][3] += a2 * b.w;
            acc[3][0] += a3 * b.x; acc[3][1] += a3 * b.y; acc[3][2] += a3 * b.z; acc[3][3] += a3 * b.w;
        }
    }

    // ---- Epilogue ----
    float bv[4];
#pragma unroll
    for (int j = 0; j < 4; j++) bv[j] = bias[n0 + tx * 4 + j];

    if (SCATTER) {
#pragma unroll
        for (int i = 0; i < 4; i++) {
            int d = rowIdx[ty * 4 + i];
            float* base = &C[(size_t)d * Nout + n0 + tx * 4];
#pragma unroll
            for (int j = 0; j < 4; j++) {
                atomicAdd(base + j, acc[i][j] + bv[j]);
            }
        }
    } else {
#pragma unroll
        for (int i = 0; i < 4; i++) {
            int gm = m0 + ty * 4 + i;
            if (gm < M) {
                float4 o;
                o.x = acc[i][0] + bv[0];
                o.y = acc[i][1] + bv[1];
                o.z = acc[i][2] + bv[2];
                o.w = acc[i][3] + bv[3];
                if (RELU) {
                    o.x = fmaxf(o.x, 0.0f);
                    o.y = fmaxf(o.y, 0.0f);
                    o.z = fmaxf(o.z, 0.0f);
                    o.w = fmaxf(o.w, 0.0f);
                }
                *reinterpret_cast<float4*>(&C[(size_t)gm * Nout + n0 + tx * 4]) = o;
            }
        }
    }
}

extern "C" void kernel_launch(void* const* d_in, const int* in_sizes, int n_in,
                              void* d_out, int out_size)
{
    const float* H         = (const float*)d_in[0];
    const int*   edge_idx  = (const int*)  d_in[1];   // [2, E] stacked: src then dst
    const float* edge_attr = (const float*)d_in[2];
    const float* eps       = (const float*)d_in[3];
    const float* msg_W1    = (const float*)d_in[4];   // [192, 256]
    const float* msg_b1    = (const float*)d_in[5];
    const float* msg_W2    = (const float*)d_in[6];   // [256, 128]
    const float* msg_b2    = (const float*)d_in[7];
    const float* self_W1   = (const float*)d_in[8];   // [128, 256]
    const float* self_b1   = (const float*)d_in[9];
    const float* self_W2   = (const float*)d_in[10];  // [256, 128]
    const float* self_b2   = (const float*)d_in[11];

    const int* src = edge_idx;
    const int* dst = edge_idx + N_EDGES;
    float* out = (float*)d_out;

    float *X1, *agg, *hid;
    cudaGetSymbolAddress((void**)&X1,  g_X1);
    cudaGetSymbolAddress((void**)&agg, g_agg);
    cudaGetSymbolAddress((void**)&hid, g_hid);

    // 0) agg = (1+eps) * H
    init_agg_kernel<<<cdiv(N_NODES * DIM, 256), 256>>>(H, eps);

    // 1) X1 = relu(concat(H[src], edge_attr) @ msg_W1 + msg_b1)   [E x 256]
    gemm_kernel<true, true, false><<<dim3(N_EDGES / BM, HID / BN), 256>>>(
        nullptr, H, edge_attr, src, nullptr,
        msg_W1, msg_b1, X1, N_EDGES, DIM + EDGE_DIM, HID);

    // 2) agg[dst[e]] += X1[e] @ msg_W2 + msg_b2                    [scatter into N x 128]
    gemm_kernel<false, false, true><<<dim3(N_EDGES / BM, DIM / BN), 256>>>(
        X1, nullptr, nullptr, nullptr, dst,
        msg_W2, msg_b2, agg, N_EDGES, HID, DIM);

    // 3) hid = relu(agg @ self_W1 + self_b1)                       [N x 256]
    gemm_kernel<false, true, false><<<dim3(cdiv(N_NODES, BM), HID / BN), 256>>>(
        agg, nullptr, nullptr, nullptr, nullptr,
        self_W1, self_b1, hid, N_NODES, DIM, HID);

    // 4) out = hid @ self_W2 + self_b2                             [N x 128]
    gemm_kernel<false, false, false><<<dim3(cdiv(N_NODES, BM), DIM / BN), 256>>>(
        hid, nullptr, nullptr, nullptr, nullptr,
        self_W2, self_b2, out, N_NODES, HID, DIM);
}

// round 5
// speedup vs baseline: 2.8127x; 2.8127x over previous
#include <cuda_runtime.h>
#include <cstdint>

// GINEdgeLayer via legacy tf32 mma.sync (m16n8k8) — tcgen05 is unavailable in
// this build (ptxas targets sm_103 without the 'a' feature set).
// out = MLP2((1+eps)*H + segment_sum(MLP1([H[src], edge_attr]), dst))

static constexpr int N_NODES  = 20000;
static constexpr int N_EDGES  = 200000;
static constexpr int DIM      = 128;
static constexpr int EDGE_DIM = 64;
static constexpr int HID      = 256;

// ---- scratch (__device__ globals; no runtime allocation allowed) ----
__device__ float g_X1 [(size_t)N_EDGES * HID];   // ~205 MB
__device__ float g_agg[(size_t)N_NODES * DIM];
__device__ float g_hid[(size_t)N_NODES * HID];
__device__ __align__(16) float g_W1c[(DIM + EDGE_DIM) * HID];  // tf32 bits, layout-preserving
__device__ __align__(16) float g_W2c[HID * DIM];
__device__ __align__(16) float g_W3c[DIM * HID];
__device__ __align__(16) float g_W4c[HID * DIM];

static inline int cdiv(int a, int b) { return (a + b - 1) / b; }

__device__ __forceinline__ uint32_t smem_u32(const void* p) {
    uint32_t a;
    asm("{ .reg .u64 t; cvta.to.shared.u64 t, %1; cvt.u32.u64 %0, t; }" : "=r"(a) : "l"(p));
    return a;
}
__device__ __forceinline__ uint32_t f2tf32(float f) {
    uint32_t r; asm("cvt.rna.tf32.f32 %0, %1;" : "=r"(r) : "f"(f)); return r;
}

__global__ __launch_bounds__(256)
void init_agg_kernel(const float* __restrict__ H, const float* __restrict__ eps) {
    int i = blockIdx.x * 256 + threadIdx.x;
    if (i < N_NODES * DIM) g_agg[i] = (1.0f + eps[0]) * H[i];
}

__global__ __launch_bounds__(256)
void cvt_tf32_kernel(const float* __restrict__ W, float* __restrict__ Wc, int n) {
    int i = blockIdx.x * 256 + threadIdx.x;
    if (i < n) Wc[i] = __uint_as_float(f2tf32(W[i]));
}

// ===================== tf32 mma.sync GEMM =====================
// C[M, NOUT](+=) op(Arows @ W + bias); W[K, NOUT] row-major, tf32-converted.
// CTA: 128(M) x 128(N) x K, chunks of 32. 8 warps (4 M x 2 N), warp tile 32x64.
// GATHER:  A row m = concat(H[src[m], :128], edge_attr[m, :64])   (K = 192)
// SCATTER: red.global.add rows into C[dst[m]] instead of store.
template<int K, int NOUT, bool GATHER, bool RELU, bool SCATTER>
__global__ void __launch_bounds__(256, 1)
gemm_mma(const float* __restrict__ A,
         const float* __restrict__ Bw,      // tf32 weights [K, NOUT]
         const float* __restrict__ bias,
         float*       __restrict__ C,
         const int*   __restrict__ idxv,
         const float* __restrict__ H,
         const float* __restrict__ EA,
         int M)
{
    constexpr int NK  = K / 32;
    constexpr int AST = 36;                  // A smem row stride (floats): conflict-free frags
    constexpr int BST = 136;                 // B smem row stride (floats): conflict-free frags
    constexpr int ABYTES = 128 * AST * 4;    // 18432
    constexpr int BBYTES = 32 * BST * 4;     // 17408

    extern __shared__ char smem[];
    int*   rowIdx = (int*)smem;                              // 512 B
    float* As0 = (float*)(smem + 512);
    float* As1 = (float*)(smem + 512 + ABYTES);
    float* Bs0 = (float*)(smem + 512 + 2 * ABYTES);
    float* Bs1 = (float*)(smem + 512 + 2 * ABYTES + BBYTES);

    const int tid  = threadIdx.x;
    const int wid  = tid >> 5, lane = tid & 31;
    const int g    = lane >> 2, t = lane & 3;    // groupID, threadID_in_group
    const int wm   = wid & 3,  wn = wid >> 2;    // warp grid 4(M) x 2(N)
    const int m0   = blockIdx.x * 128;
    const int nb0  = blockIdx.y * 128;           // N-block offset within NOUT

    if ((GATHER || SCATTER) && tid < 128) {
        int gm = m0 + tid;
        rowIdx[tid] = idxv[gm < M ? gm : M - 1];
    }
    __syncthreads();

    // ---- A staging: thread (row = tid/2, half = tid&1) handles 16 floats ----
    const int ar = tid >> 1, ah = tid & 1;
    int agm = m0 + ar; if (agm >= M) agm = M - 1;

    auto lda = [&](int kc, float4* v) {
        int k0 = kc * 32 + ah * 16;
        const float* src;
        if (GATHER) {
            src = (k0 < DIM) ? H + (size_t)rowIdx[ar] * DIM + k0
                             : EA + (size_t)agm * EDGE_DIM + (k0 - DIM);
        } else {
            src = A + (size_t)agm * K + k0;
        }
#pragma unroll
        for (int j = 0; j < 4; j++) v[j] = *reinterpret_cast<const float4*>(src + j * 4);
    };
    auto sta = [&](float* buf, const float4* v) {
        float* d = buf + ar * AST + ah * 16;
#pragma unroll
        for (int j = 0; j < 4; j++) {
            uint4 u;
            u.x = f2tf32(v[j].x); u.y = f2tf32(v[j].y);
            u.z = f2tf32(v[j].z); u.w = f2tf32(v[j].w);
            *reinterpret_cast<uint4*>(d + j * 4) = u;
        }
    };

    // ---- B staging via cp.async: thread (k = tid/8, colbase = (tid&7)*16) ----
    const int bkr = tid >> 3;
    const int bc0 = (tid & 7) * 16;
    const float* bgbase = Bw + nb0 + bc0;
    auto ldb = [&](int kc, float* buf) {
        uint32_t d = smem_u32(buf + bkr * BST + bc0);
        const float* s = bgbase + (size_t)(kc * 32 + bkr) * NOUT;
#pragma unroll
        for (int j = 0; j < 4; j++)
            asm volatile("cp.async.cg.shared.global [%0], [%1], 16;"
                         :: "r"(d + j * 16), "l"(s + j * 4) : "memory");
        asm volatile("cp.async.commit_group;" ::: "memory");
    };

    float acc[2][8][4];
#pragma unroll
    for (int mi = 0; mi < 2; mi++)
#pragma unroll
        for (int ni = 0; ni < 8; ni++)
#pragma unroll
            for (int r = 0; r < 4; r++) acc[mi][ni][r] = 0.0f;

    // ---- prologue ----
    float4 av[4];
    ldb(0, Bs0);
    lda(0, av);
    sta(As0, av);
    asm volatile("cp.async.wait_group 0;" ::: "memory");
    __syncthreads();

    // ---- main loop ----
#pragma unroll 1
    for (int kc = 0; kc < NK; kc++) {
        const int p = kc & 1;
        float* Acur = p ? As1 : As0;
        float* Bcur = p ? Bs1 : Bs0;
        float* Anxt = p ? As0 : As1;
        float* Bnxt = p ? Bs0 : Bs1;

        if (kc + 1 < NK) { ldb(kc + 1, Bnxt); lda(kc + 1, av); }

#pragma unroll
        for (int kk = 0; kk < 4; kk++) {
            const int k0 = kk * 8;
            uint32_t af[2][4];
#pragma unroll
            for (int mi = 0; mi < 2; mi++) {
                const float* ap = Acur + (wm * 32 + mi * 16 + g) * AST + k0 + t;
                af[mi][0] = __float_as_uint(ap[0]);
                af[mi][1] = __float_as_uint(ap[8 * AST]);
                af[mi][2] = __float_as_uint(ap[4]);
                af[mi][3] = __float_as_uint(ap[8 * AST + 4]);
            }
#pragma unroll
            for (int ni = 0; ni < 8; ni++) {
                const float* bp = Bcur + (k0 + t) * BST + wn * 64 + ni * 8 + g;
                uint32_t b0 = __float_as_uint(bp[0]);
                uint32_t b1 = __float_as_uint(bp[4 * BST]);
#pragma unroll
                for (int mi = 0; mi < 2; mi++) {
                    asm volatile(
                        "mma.sync.aligned.m16n8k8.row.col.f32.tf32.tf32.f32 "
                        "{%0,%1,%2,%3}, {%4,%5,%6,%7}, {%8,%9}, {%0,%1,%2,%3};"
                        : "+f"(acc[mi][ni][0]), "+f"(acc[mi][ni][1]),
                          "+f"(acc[mi][ni][2]), "+f"(acc[mi][ni][3])
                        : "r"(af[mi][0]), "r"(af[mi][1]), "r"(af[mi][2]), "r"(af[mi][3]),
                          "r"(b0), "r"(b1));
                }
            }
        }

        if (kc + 1 < NK) {
            sta(Anxt, av);
            asm volatile("cp.async.wait_group 0;" ::: "memory");
        }
        __syncthreads();
    }

    // ---- epilogue ----
    float2 bv[8];
#pragma unroll
    for (int ni = 0; ni < 8; ni++)
        bv[ni] = *reinterpret_cast<const float2*>(bias + nb0 + wn * 64 + ni * 8 + 2 * t);

#pragma unroll
    for (int mi = 0; mi < 2; mi++) {
#pragma unroll
        for (int half = 0; half < 2; half++) {
            const int row_l = wm * 32 + mi * 16 + g + half * 8;
            const int gm = m0 + row_l;
            if (gm < M) {
                const size_t orow = SCATTER ? (size_t)rowIdx[row_l] : (size_t)gm;
                float* cp = C + orow * NOUT + nb0 + wn * 64 + 2 * t;
#pragma unroll
                for (int ni = 0; ni < 8; ni++) {
                    float x = acc[mi][ni][half * 2 + 0] + bv[ni].x;
                    float y = acc[mi][ni][half * 2 + 1] + bv[ni].y;
                    if (RELU) { x = fmaxf(x, 0.0f); y = fmaxf(y, 0.0f); }
                    if (SCATTER) {
                        asm volatile("red.global.add.v2.f32 [%0], {%1, %2};"
                                     :: "l"(cp + ni * 8), "f"(x), "f"(y) : "memory");
                    } else {
                        *reinterpret_cast<float2*>(cp + ni * 8) = make_float2(x, y);
                    }
                }
            }
        }
    }
}

// ===================== launch =====================
extern "C" void kernel_launch(void* const* d_in, const int* in_sizes, int n_in,
                              void* d_out, int out_size)
{
    const float* H         = (const float*)d_in[0];
    const int*   edge_idx  = (const int*)  d_in[1];
    const float* edge_attr = (const float*)d_in[2];
    const float* eps       = (const float*)d_in[3];
    const float* msg_W1    = (const float*)d_in[4];
    const float* msg_b1    = (const float*)d_in[5];
    const float* msg_W2    = (const float*)d_in[6];
    const float* msg_b2    = (const float*)d_in[7];
    const float* self_W1   = (const float*)d_in[8];
    const float* self_b1   = (const float*)d_in[9];
    const float* self_W2   = (const float*)d_in[10];
    const float* self_b2   = (const float*)d_in[11];

    const int* src = edge_idx;
    const int* dst = edge_idx + N_EDGES;
    float* out = (float*)d_out;

    float *X1, *agg, *hid, *W1c, *W2c, *W3c, *W4c;
    cudaGetSymbolAddress((void**)&X1,  g_X1);
    cudaGetSymbolAddress((void**)&agg, g_agg);
    cudaGetSymbolAddress((void**)&hid, g_hid);
    cudaGetSymbolAddress((void**)&W1c, g_W1c);
    cudaGetSymbolAddress((void**)&W2c, g_W2c);
    cudaGetSymbolAddress((void**)&W3c, g_W3c);
    cudaGetSymbolAddress((void**)&W4c, g_W4c);

    constexpr int K1 = DIM + EDGE_DIM;  // 192
    constexpr int SMEM = 512 + 2 * (128 * 36 * 4) + 2 * (32 * 136 * 4);  // 72192

    cudaFuncSetAttribute((const void*)gemm_mma<K1,  HID, true,  true,  false>,
                         cudaFuncAttributeMaxDynamicSharedMemorySize, SMEM);
    cudaFuncSetAttribute((const void*)gemm_mma<HID, DIM, false, false, true>,
                         cudaFuncAttributeMaxDynamicSharedMemorySize, SMEM);
    cudaFuncSetAttribute((const void*)gemm_mma<DIM, HID, false, true,  false>,
                         cudaFuncAttributeMaxDynamicSharedMemorySize, SMEM);
    cudaFuncSetAttribute((const void*)gemm_mma<HID, DIM, false, false, false>,
                         cudaFuncAttributeMaxDynamicSharedMemorySize, SMEM);

    // 0) agg = (1+eps)*H ; convert weights to tf32 bits (layout preserved)
    init_agg_kernel<<<cdiv(N_NODES * DIM, 256), 256>>>(H, eps);
    cvt_tf32_kernel<<<cdiv(K1  * HID, 256), 256>>>(msg_W1,  W1c, K1  * HID);
    cvt_tf32_kernel<<<cdiv(HID * DIM, 256), 256>>>(msg_W2,  W2c, HID * DIM);
    cvt_tf32_kernel<<<cdiv(DIM * HID, 256), 256>>>(self_W1, W3c, DIM * HID);
    cvt_tf32_kernel<<<cdiv(HID * DIM, 256), 256>>>(self_W2, W4c, HID * DIM);

    // 1) X1 = relu(concat(H[src], edge_attr) @ msg_W1 + msg_b1)   [E, 256]
    gemm_mma<K1, HID, true, true, false><<<dim3(cdiv(N_EDGES, 128), 2), 256, SMEM>>>(
        nullptr, W1c, msg_b1, X1, src, H, edge_attr, N_EDGES);

    // 2) agg[dst[e]] += X1[e] @ msg_W2 + msg_b2                    (scatter, [N,128])
    gemm_mma<HID, DIM, false, false, true><<<dim3(cdiv(N_EDGES, 128), 1), 256, SMEM>>>(
        X1, W2c, msg_b2, agg, dst, nullptr, nullptr, N_EDGES);

    // 3) hid = relu(agg @ self_W1 + self_b1)                       [N, 256]
    gemm_mma<DIM, HID, false, true, false><<<dim3(cdiv(N_NODES, 128), 2), 256, SMEM>>>(
        agg, W3c, self_b1, hid, nullptr, nullptr, nullptr, N_NODES);

    // 4) out = hid @ self_W2 + self_b2                             [N, 128]
    gemm_mma<HID, DIM, false, false, false><<<dim3(cdiv(N_NODES, 128), 1), 256, SMEM>>>(
        hid, W4c, self_b2, out, nullptr, nullptr, nullptr, N_NODES);
}

// round 6
// speedup vs baseline: 3.2268x; 1.1472x over previous
#include <cuda_runtime.h>
#include <cstdint>

// GINEdgeLayer, fused two-layer MLPs on legacy tf32 mma.sync (m16n8k8).
// out = MLP2((1+eps)*H + segment_sum(MLP1([H[src], edge_attr]), dst))
//
// Launches: init_agg, cvt x4, fused_edge (MLP1 + scatter), fused_node (MLP2).

static constexpr int N_NODES  = 20000;
static constexpr int N_EDGES  = 200000;
static constexpr int DIM      = 128;
static constexpr int EDGE_DIM = 64;
static constexpr int HID      = 256;

// ---- scratch (__device__ globals; no runtime allocation allowed) ----
__device__ float g_agg[(size_t)N_NODES * DIM];
__device__ __align__(16) float g_W1c[(DIM + EDGE_DIM) * HID];  // tf32 bits, layout preserved
__device__ __align__(16) float g_W2c[HID * DIM];
__device__ __align__(16) float g_W3c[DIM * HID];
__device__ __align__(16) float g_W4c[HID * DIM];

static inline int cdiv(int a, int b) { return (a + b - 1) / b; }

__device__ __forceinline__ uint32_t smem_u32(const void* p) {
    uint32_t a;
    asm("{ .reg .u64 t; cvta.to.shared.u64 t, %1; cvt.u32.u64 %0, t; }" : "=r"(a) : "l"(p));
    return a;
}
__device__ __forceinline__ uint32_t f2tf32(float f) {
    uint32_t r; asm("cvt.rna.tf32.f32 %0, %1;" : "=r"(r) : "f"(f)); return r;
}

__global__ __launch_bounds__(256)
void init_agg_kernel(const float* __restrict__ H, const float* __restrict__ eps) {
    int i = blockIdx.x * 256 + threadIdx.x;
    if (i < N_NODES * DIM) g_agg[i] = (1.0f + eps[0]) * H[i];
}

__global__ __launch_bounds__(256)
void cvt_tf32_kernel(const float* __restrict__ W, float* __restrict__ Wc, int n) {
    int i = blockIdx.x * 256 + threadIdx.x;
    if (i < n) Wc[i] = __uint_as_float(f2tf32(W[i]));
}

// =====================================================================
// Fused 2-layer MLP, CTA tile = 128 rows.
//   stage 1: X1 = relu(rowsA @ W1 + b1)            [128, 256] kept in SMEM (tf32 bits)
//   stage 2: Y  = X1 @ W2 + b2                     [128, 128]
// EDGE: rowsA[m] = concat(H[src[m]], edge_attr[m]) (K1=192); Y scattered
//       via red.global.add into Cout[dst[m]].
// !EDGE: rowsA = Ain (K1=128); Y stored to Cout rows.
// 8 warps: wm = wid&3 (M 4x32), wn = wid>>2 (N 2x64).
// =====================================================================
template<int K1, bool EDGE>
__global__ void __launch_bounds__(256, 1)
fused_mlp(const float* __restrict__ Ain,
          const float* __restrict__ W1c, const float* __restrict__ b1,
          const float* __restrict__ W2c, const float* __restrict__ b2,
          float*       __restrict__ Cout,
          const int*   __restrict__ srcv, const int* __restrict__ dstv,
          const float* __restrict__ H,   const float* __restrict__ EA,
          int M)
{
    constexpr int NK1 = K1 / 32;
    constexpr int NK2 = HID / 32;          // 8
    constexpr int AST = 36;                // A smem stride (floats)
    constexpr int BST = 136;               // B smem stride
    constexpr int XST = 260;               // X1 smem stride (260%32==4 -> conflict-free frags)
    constexpr int ABYTES = 128 * AST * 4;  // 18432
    constexpr int BBYTES = 32 * BST * 4;   // 17408
    // layout: [idx 1024][As0][As1][Bs0][Bs1][X1 128*260*4]
    constexpr int OFF_A  = 1024;
    constexpr int OFF_B  = OFF_A + 2 * ABYTES;            // 37888
    constexpr int OFF_X  = OFF_B + 2 * BBYTES;            // 72704
    // total = 72704 + 133120 = 205824

    extern __shared__ char smem[];
    int*   srcIdx = (int*)smem;
    int*   dstIdx = (int*)(smem + 512);
    float* As0 = (float*)(smem + OFF_A);
    float* As1 = (float*)(smem + OFF_A + ABYTES);
    float* Bs0 = (float*)(smem + OFF_B);
    float* Bs1 = (float*)(smem + OFF_B + BBYTES);
    float* X1  = (float*)(smem + OFF_X);

    const int tid  = threadIdx.x;
    const int wid  = tid >> 5, lane = tid & 31;
    const int g    = lane >> 2, t = lane & 3;
    const int wm   = wid & 3,  wn = wid >> 2;
    const int m0   = blockIdx.x * 128;

    if (EDGE && tid < 128) {
        int gm = m0 + tid;
        int cm = gm < M ? gm : M - 1;
        srcIdx[tid] = srcv[cm];
        dstIdx[tid] = dstv[cm];
    }
    __syncthreads();

    // ---- stage-1 A staging: thread (row=tid/2, half=tid&1) handles 16 floats ----
    const int ar = tid >> 1, ah = tid & 1;
    int agm = m0 + ar; if (agm >= M) agm = M - 1;

    auto lda = [&](int kc, float4* v) {
        int k0 = kc * 32 + ah * 16;
        const float* s;
        if (EDGE) {
            s = (k0 < DIM) ? H + (size_t)srcIdx[ar] * DIM + k0
                           : EA + (size_t)agm * EDGE_DIM + (k0 - DIM);
        } else {
            s = Ain + (size_t)agm * K1 + k0;
        }
#pragma unroll
        for (int j = 0; j < 4; j++) v[j] = *reinterpret_cast<const float4*>(s + j * 4);
    };
    auto sta = [&](float* buf, const float4* v) {
        float* d = buf + ar * AST + ah * 16;
#pragma unroll
        for (int j = 0; j < 4; j++) {
            uint4 u;
            u.x = f2tf32(v[j].x); u.y = f2tf32(v[j].y);
            u.z = f2tf32(v[j].z); u.w = f2tf32(v[j].w);
            *reinterpret_cast<uint4*>(d + j * 4) = u;
        }
    };

    // ---- B staging via cp.async: thread loads row bkr, 16 cols at bc0 ----
    const int bkr = tid >> 3;
    const int bc0 = (tid & 7) * 16;
    auto ldb = [&](const float* Bsrc, int ncols, int kc, int c0, float* buf) {
        uint32_t d = smem_u32(buf + bkr * BST + bc0);
        const float* s = Bsrc + (size_t)(kc * 32 + bkr) * ncols + c0 + bc0;
#pragma unroll
        for (int j = 0; j < 4; j++)
            asm volatile("cp.async.cg.shared.global [%0], [%1], 16;"
                         :: "r"(d + j * 16), "l"(s + j * 4) : "memory");
        asm volatile("cp.async.commit_group;" ::: "memory");
    };

    float acc[2][8][4];
    float4 av[4];

    // ================= stage 1: two N-halves of 128 =================
#pragma unroll 1
    for (int nh = 0; nh < 2; nh++) {
#pragma unroll
        for (int mi = 0; mi < 2; mi++)
#pragma unroll
            for (int ni = 0; ni < 8; ni++)
#pragma unroll
                for (int r = 0; r < 4; r++) acc[mi][ni][r] = 0.0f;

        ldb(W1c, HID, 0, nh * 128, Bs0);
        lda(0, av);
        sta(As0, av);
        asm volatile("cp.async.wait_group 0;" ::: "memory");
        __syncthreads();

#pragma unroll 1
        for (int kc = 0; kc < NK1; kc++) {
            const int p = kc & 1;
            float* Acur = p ? As1 : As0;
            float* Bcur = p ? Bs1 : Bs0;
            float* Anxt = p ? As0 : As1;
            float* Bnxt = p ? Bs0 : Bs1;

            if (kc + 1 < NK1) { ldb(W1c, HID, kc + 1, nh * 128, Bnxt); lda(kc + 1, av); }

#pragma unroll
            for (int kk = 0; kk < 4; kk++) {
                const int k0 = kk * 8;
                uint32_t af[2][4];
#pragma unroll
                for (int mi = 0; mi < 2; mi++) {
                    const float* ap = Acur + (wm * 32 + mi * 16 + g) * AST + k0 + t;
                    af[mi][0] = __float_as_uint(ap[0]);
                    af[mi][1] = __float_as_uint(ap[8 * AST]);
                    af[mi][2] = __float_as_uint(ap[4]);
                    af[mi][3] = __float_as_uint(ap[8 * AST + 4]);
                }
#pragma unroll
                for (int ni = 0; ni < 8; ni++) {
                    const float* bp = Bcur + (k0 + t) * BST + wn * 64 + ni * 8 + g;
                    uint32_t b0 = __float_as_uint(bp[0]);
                    uint32_t b1 = __float_as_uint(bp[4 * BST]);
#pragma unroll
                    for (int mi = 0; mi < 2; mi++) {
                        asm volatile(
                            "mma.sync.aligned.m16n8k8.row.col.f32.tf32.tf32.f32 "
                            "{%0,%1,%2,%3}, {%4,%5,%6,%7}, {%8,%9}, {%0,%1,%2,%3};"
                            : "+f"(acc[mi][ni][0]), "+f"(acc[mi][ni][1]),
                              "+f"(acc[mi][ni][2]), "+f"(acc[mi][ni][3])
                            : "r"(af[mi][0]), "r"(af[mi][1]), "r"(af[mi][2]), "r"(af[mi][3]),
                              "r"(b0), "r"(b1));
                    }
                }
            }

            if (kc + 1 < NK1) {
                sta(Anxt, av);
                asm volatile("cp.async.wait_group 0;" ::: "memory");
            }
            __syncthreads();
        }

        // epilogue: bias + relu, tf32-convert, store into X1 smem
        float2 bv[8];
#pragma unroll
        for (int ni = 0; ni < 8; ni++)
            bv[ni] = *reinterpret_cast<const float2*>(b1 + nh * 128 + wn * 64 + ni * 8 + 2 * t);

#pragma unroll
        for (int mi = 0; mi < 2; mi++)
#pragma unroll
            for (int half = 0; half < 2; half++) {
                const int row = wm * 32 + mi * 16 + g + half * 8;
                float* xp = X1 + (size_t)row * XST + nh * 128 + wn * 64 + 2 * t;
#pragma unroll
                for (int ni = 0; ni < 8; ni++) {
                    float x = fmaxf(acc[mi][ni][half * 2 + 0] + bv[ni].x, 0.0f);
                    float y = fmaxf(acc[mi][ni][half * 2 + 1] + bv[ni].y, 0.0f);
                    uint2 u; u.x = f2tf32(x); u.y = f2tf32(y);
                    *reinterpret_cast<uint2*>(xp + ni * 8) = u;
                }
            }
        // next nh's prologue syncs before reuse of A/B buffers
    }

    // ================= stage 2: Y = X1 @ W2 + b2 (K = 256) =================
#pragma unroll
    for (int mi = 0; mi < 2; mi++)
#pragma unroll
        for (int ni = 0; ni < 8; ni++)
#pragma unroll
            for (int r = 0; r < 4; r++) acc[mi][ni][r] = 0.0f;

    ldb(W2c, DIM, 0, 0, Bs0);
    asm volatile("cp.async.wait_group 0;" ::: "memory");
    __syncthreads();                        // also makes X1 visible to all warps

#pragma unroll 1
    for (int kc = 0; kc < NK2; kc++) {
        const int p = kc & 1;
        float* Bcur = p ? Bs1 : Bs0;
        float* Bnxt = p ? Bs0 : Bs1;

        if (kc + 1 < NK2) ldb(W2c, DIM, kc + 1, 0, Bnxt);

#pragma unroll
        for (int kk = 0; kk < 4; kk++) {
            const int k0 = kc * 32 + kk * 8;
            uint32_t af[2][4];
#pragma unroll
            for (int mi = 0; mi < 2; mi++) {
                const float* ap = X1 + (size_t)(wm * 32 + mi * 16 + g) * XST + k0 + t;
                af[mi][0] = __float_as_uint(ap[0]);
                af[mi][1] = __float_as_uint(ap[8 * XST]);
                af[mi][2] = __float_as_uint(ap[4]);
                af[mi][3] = __float_as_uint(ap[8 * XST + 4]);
            }
#pragma unroll
            for (int ni = 0; ni < 8; ni++) {
                const float* bp = Bcur + (kk * 8 + t) * BST + wn * 64 + ni * 8 + g;
                uint32_t b0 = __float_as_uint(bp[0]);
                uint32_t b1r = __float_as_uint(bp[4 * BST]);
#pragma unroll
                for (int mi = 0; mi < 2; mi++) {
                    asm volatile(
                        "mma.sync.aligned.m16n8k8.row.col.f32.tf32.tf32.f32 "
                        "{%0,%1,%2,%3}, {%4,%5,%6,%7}, {%8,%9}, {%0,%1,%2,%3};"
                        : "+f"(acc[mi][ni][0]), "+f"(acc[mi][ni][1]),
                          "+f"(acc[mi][ni][2]), "+f"(acc[mi][ni][3])
                        : "r"(af[mi][0]), "r"(af[mi][1]), "r"(af[mi][2]), "r"(af[mi][3]),
                          "r"(b0), "r"(b1r));
                }
            }
        }

        if (kc + 1 < NK2)
            asm volatile("cp.async.wait_group 0;" ::: "memory");
        __syncthreads();
    }

    // ---- stage-2 epilogue ----
    float2 bv[8];
#pragma unroll
    for (int ni = 0; ni < 8; ni++)
        bv[ni] = *reinterpret_cast<const float2*>(b2 + wn * 64 + ni * 8 + 2 * t);

#pragma unroll
    for (int mi = 0; mi < 2; mi++)
#pragma unroll
        for (int half = 0; half < 2; half++) {
            const int row_l = wm * 32 + mi * 16 + g + half * 8;
            const int gm = m0 + row_l;
            if (gm < M) {
                const size_t orow = EDGE ? (size_t)dstIdx[row_l] : (size_t)gm;
                float* cp = Cout + orow * DIM + wn * 64 + 2 * t;
#pragma unroll
                for (int ni = 0; ni < 8; ni++) {
                    float x = acc[mi][ni][half * 2 + 0] + bv[ni].x;
                    float y = acc[mi][ni][half * 2 + 1] + bv[ni].y;
                    if (EDGE) {
                        asm volatile("red.global.add.v2.f32 [%0], {%1, %2};"
                                     :: "l"(cp + ni * 8), "f"(x), "f"(y) : "memory");
                    } else {
                        *reinterpret_cast<float2*>(cp + ni * 8) = make_float2(x, y);
                    }
                }
            }
        }
}

// ===================== launch =====================
extern "C" void kernel_launch(void* const* d_in, const int* in_sizes, int n_in,
                              void* d_out, int out_size)
{
    const float* H         = (const float*)d_in[0];
    const int*   edge_idx  = (const int*)  d_in[1];
    const float* edge_attr = (const float*)d_in[2];
    const float* eps       = (const float*)d_in[3];
    const float* msg_W1    = (const float*)d_in[4];
    const float* msg_b1    = (const float*)d_in[5];
    const float* msg_W2    = (const float*)d_in[6];
    const float* msg_b2    = (const float*)d_in[7];
    const float* self_W1   = (const float*)d_in[8];
    const float* self_b1   = (const float*)d_in[9];
    const float* self_W2   = (const float*)d_in[10];
    const float* self_b2   = (const float*)d_in[11];

    const int* src = edge_idx;
    const int* dst = edge_idx + N_EDGES;
    float* out = (float*)d_out;

    float *agg, *W1c, *W2c, *W3c, *W4c;
    cudaGetSymbolAddress((void**)&agg, g_agg);
    cudaGetSymbolAddress((void**)&W1c, g_W1c);
    cudaGetSymbolAddress((void**)&W2c, g_W2c);
    cudaGetSymbolAddress((void**)&W3c, g_W3c);
    cudaGetSymbolAddress((void**)&W4c, g_W4c);

    constexpr int K1 = DIM + EDGE_DIM;  // 192
    constexpr int SMEM = 1024 + 2 * (128 * 36 * 4) + 2 * (32 * 136 * 4)
                       + 128 * 260 * 4;  // 205824

    cudaFuncSetAttribute((const void*)fused_mlp<K1, true>,
                         cudaFuncAttributeMaxDynamicSharedMemorySize, SMEM);
    cudaFuncSetAttribute((const void*)fused_mlp<DIM, false>,
                         cudaFuncAttributeMaxDynamicSharedMemorySize, SMEM);

    // 0) agg = (1+eps)*H ; weights -> tf32 bits (5 launches keep ncu -s 5 on edge kernel)
    init_agg_kernel<<<cdiv(N_NODES * DIM, 256), 256>>>(H, eps);
    cvt_tf32_kernel<<<cdiv(K1  * HID, 256), 256>>>(msg_W1,  W1c, K1  * HID);
    cvt_tf32_kernel<<<cdiv(HID * DIM, 256), 256>>>(msg_W2,  W2c, HID * DIM);
    cvt_tf32_kernel<<<cdiv(DIM * HID, 256), 256>>>(self_W1, W3c, DIM * HID);
    cvt_tf32_kernel<<<cdiv(HID * DIM, 256), 256>>>(self_W2, W4c, HID * DIM);

    // 1) fused edge MLP + scatter into agg
    fused_mlp<K1, true><<<cdiv(N_EDGES, 128), 256, SMEM>>>(
        nullptr, W1c, msg_b1, W2c, msg_b2, agg, src, dst, H, edge_attr, N_EDGES);

    // 2) fused node MLP -> out
    fused_mlp<DIM, false><<<cdiv(N_NODES, 128), 256, SMEM>>>(
        agg, W3c, self_b1, W4c, self_b2, out, nullptr, nullptr, nullptr, nullptr, N_NODES);
}

// round 7
// speedup vs baseline: 3.2740x; 1.0146x over previous
#include <cuda_runtime.h>
#include <cstdint>

// GINEdgeLayer, fused two-layer MLPs on legacy tf32 mma.sync (m16n8k8).
// out = MLP2((1+eps)*H + segment_sum(MLP1([H[src], edge_attr]), dst))
//
// Launch order (capture lands on index 3 = fused edge kernel):
//   0: init_agg   1: cvt_msg   2: cvt_self   3: fused_edge   4: fused_node

static constexpr int N_NODES  = 20000;
static constexpr int N_EDGES  = 200000;
static constexpr int DIM      = 128;
static constexpr int EDGE_DIM = 64;
static constexpr int HID      = 256;

// ---- scratch (__device__ globals; no runtime allocation allowed) ----
__device__ float g_agg[(size_t)N_NODES * DIM];
__device__ __align__(16) float g_W1c[(DIM + EDGE_DIM) * HID];  // tf32 bits, layout preserved
__device__ __align__(16) float g_W2c[HID * DIM];
__device__ __align__(16) float g_W3c[DIM * HID];
__device__ __align__(16) float g_W4c[HID * DIM];

static inline int cdiv(int a, int b) { return (a + b - 1) / b; }

__device__ __forceinline__ uint32_t smem_u32(const void* p) {
    uint32_t a;
    asm("{ .reg .u64 t; cvta.to.shared.u64 t, %1; cvt.u32.u64 %0, t; }" : "=r"(a) : "l"(p));
    return a;
}
__device__ __forceinline__ uint32_t f2tf32(float f) {
    uint32_t r; asm("cvt.rna.tf32.f32 %0, %1;" : "=r"(r) : "f"(f)); return r;
}

__global__ __launch_bounds__(256)
void init_agg_kernel(const float* __restrict__ H, const float* __restrict__ eps) {
    int i = blockIdx.x * 256 + threadIdx.x;
    if (i < N_NODES * DIM) g_agg[i] = (1.0f + eps[0]) * H[i];
}

// Converts two weight matrices in one launch (keeps edge kernel at launch idx 3).
__global__ __launch_bounds__(256)
void cvt2_tf32_kernel(const float* __restrict__ Wa, float* __restrict__ WaC, int na,
                      const float* __restrict__ Wb, float* __restrict__ WbC, int nb) {
    int i = blockIdx.x * 256 + threadIdx.x;
    if (i < na)           WaC[i]      = __uint_as_float(f2tf32(Wa[i]));
    else if (i < na + nb) WbC[i - na] = __uint_as_float(f2tf32(Wb[i - na]));
}

// =====================================================================
// Fused 2-layer MLP, CTA tile = 128 rows.
//   stage 1: X1 = relu(rowsA @ W1 + b1)            [128, 256] kept in SMEM (tf32 bits)
//   stage 2: Y  = X1 @ W2 + b2                     [128, 128]
// EDGE: rowsA[m] = concat(H[src[m]], edge_attr[m]) (K1=192); Y scattered
//       via red.global.add into Cout[dst[m]].
// !EDGE: rowsA = Ain (K1=128); Y stored to Cout rows.
// 8 warps: wm = wid&3 (M 4x32), wn = wid>>2 (N 2x64).
// =====================================================================
template<int K1, bool EDGE>
__global__ void __launch_bounds__(256, 1)
fused_mlp(const float* __restrict__ Ain,
          const float* __restrict__ W1c, const float* __restrict__ b1,
          const float* __restrict__ W2c, const float* __restrict__ b2,
          float*       __restrict__ Cout,
          const int*   __restrict__ srcv, const int* __restrict__ dstv,
          const float* __restrict__ H,   const float* __restrict__ EA,
          int M)
{
    constexpr int NK1 = K1 / 32;
    constexpr int NK2 = HID / 32;          // 8
    constexpr int AST = 36;                // A smem stride (floats)
    constexpr int BST = 136;               // B smem stride
    constexpr int XST = 260;               // X1 smem stride (260%32==4 -> conflict-free frags)
    constexpr int ABYTES = 128 * AST * 4;  // 18432
    constexpr int BBYTES = 32 * BST * 4;   // 17408
    constexpr int OFF_A  = 1024;
    constexpr int OFF_B  = OFF_A + 2 * ABYTES;            // 37888
    constexpr int OFF_X  = OFF_B + 2 * BBYTES;            // 72704
    // total = 72704 + 133120 = 205824
    static_assert((NK1 & 1) == 0, "stage-2 prefetch assumes even NK1 (Bs0 free)");

    extern __shared__ char smem[];
    int*   srcIdx = (int*)smem;
    int*   dstIdx = (int*)(smem + 512);
    float* As0 = (float*)(smem + OFF_A);
    float* As1 = (float*)(smem + OFF_A + ABYTES);
    float* Bs0 = (float*)(smem + OFF_B);
    float* Bs1 = (float*)(smem + OFF_B + BBYTES);
    float* X1  = (float*)(smem + OFF_X);

    const int tid  = threadIdx.x;
    const int wid  = tid >> 5, lane = tid & 31;
    const int g    = lane >> 2, t = lane & 3;
    const int wm   = wid & 3,  wn = wid >> 2;
    const int m0   = blockIdx.x * 128;

    if (EDGE && tid < 128) {
        int gm = m0 + tid;
        int cm = gm < M ? gm : M - 1;
        srcIdx[tid] = srcv[cm];
        dstIdx[tid] = dstv[cm];
    }
    __syncthreads();

    // ---- stage-1 A staging: thread (row=tid/2, half=tid&1) handles 16 floats ----
    const int ar = tid >> 1, ah = tid & 1;
    int agm = m0 + ar; if (agm >= M) agm = M - 1;

    auto lda = [&](int kc, float4* v) {
        int k0 = kc * 32 + ah * 16;
        const float* s;
        if (EDGE) {
            s = (k0 < DIM) ? H + (size_t)srcIdx[ar] * DIM + k0
                           : EA + (size_t)agm * EDGE_DIM + (k0 - DIM);
        } else {
            s = Ain + (size_t)agm * K1 + k0;
        }
#pragma unroll
        for (int j = 0; j < 4; j++) v[j] = *reinterpret_cast<const float4*>(s + j * 4);
    };
    auto sta = [&](float* buf, const float4* v) {
        float* d = buf + ar * AST + ah * 16;
#pragma unroll
        for (int j = 0; j < 4; j++) {
            uint4 u;
            u.x = f2tf32(v[j].x); u.y = f2tf32(v[j].y);
            u.z = f2tf32(v[j].z); u.w = f2tf32(v[j].w);
            *reinterpret_cast<uint4*>(d + j * 4) = u;
        }
    };

    // ---- B staging via cp.async: thread loads row bkr, 16 cols at bc0 ----
    const int bkr = tid >> 3;
    const int bc0 = (tid & 7) * 16;
    auto ldb = [&](const float* Bsrc, int ncols, int kc, int c0, float* buf) {
        uint32_t d = smem_u32(buf + bkr * BST + bc0);
        const float* s = Bsrc + (size_t)(kc * 32 + bkr) * ncols + c0 + bc0;
#pragma unroll
        for (int j = 0; j < 4; j++)
            asm volatile("cp.async.cg.shared.global [%0], [%1], 16;"
                         :: "r"(d + j * 16), "l"(s + j * 4) : "memory");
        asm volatile("cp.async.commit_group;" ::: "memory");
    };

    float acc[2][8][4];
    float4 av[4];

    // ================= stage 1: two N-halves of 128 =================
#pragma unroll 1
    for (int nh = 0; nh < 2; nh++) {
#pragma unroll
        for (int mi = 0; mi < 2; mi++)
#pragma unroll
            for (int ni = 0; ni < 8; ni++)
#pragma unroll
                for (int r = 0; r < 4; r++) acc[mi][ni][r] = 0.0f;

        ldb(W1c, HID, 0, nh * 128, Bs0);
        lda(0, av);
        sta(As0, av);
        asm volatile("cp.async.wait_group 0;" ::: "memory");
        __syncthreads();

#pragma unroll 1
        for (int kc = 0; kc < NK1; kc++) {
            const int p = kc & 1;
            float* Acur = p ? As1 : As0;
            float* Bcur = p ? Bs1 : Bs0;
            float* Anxt = p ? As0 : As1;
            float* Bnxt = p ? Bs0 : Bs1;

            if (kc + 1 < NK1) { ldb(W1c, HID, kc + 1, nh * 128, Bnxt); lda(kc + 1, av); }

#pragma unroll
            for (int kk = 0; kk < 4; kk++) {
                const int k0 = kk * 8;
                uint32_t af[2][4];
#pragma unroll
                for (int mi = 0; mi < 2; mi++) {
                    const float* ap = Acur + (wm * 32 + mi * 16 + g) * AST + k0 + t;
                    af[mi][0] = __float_as_uint(ap[0]);
                    af[mi][1] = __float_as_uint(ap[8 * AST]);
                    af[mi][2] = __float_as_uint(ap[4]);
                    af[mi][3] = __float_as_uint(ap[8 * AST + 4]);
                }
#pragma unroll
                for (int ni = 0; ni < 8; ni++) {
                    const float* bp = Bcur + (k0 + t) * BST + wn * 64 + ni * 8 + g;
                    uint32_t b0 = __float_as_uint(bp[0]);
                    uint32_t b1r = __float_as_uint(bp[4 * BST]);
#pragma unroll
                    for (int mi = 0; mi < 2; mi++) {
                        asm volatile(
                            "mma.sync.aligned.m16n8k8.row.col.f32.tf32.tf32.f32 "
                            "{%0,%1,%2,%3}, {%4,%5,%6,%7}, {%8,%9}, {%0,%1,%2,%3};"
                            : "+f"(acc[mi][ni][0]), "+f"(acc[mi][ni][1]),
                              "+f"(acc[mi][ni][2]), "+f"(acc[mi][ni][3])
                            : "r"(af[mi][0]), "r"(af[mi][1]), "r"(af[mi][2]), "r"(af[mi][3]),
                              "r"(b0), "r"(b1r));
                    }
                }
            }

            if (kc + 1 < NK1) {
                sta(Anxt, av);
                asm volatile("cp.async.wait_group 0;" ::: "memory");
            }
            __syncthreads();
        }

        // stage-2 chunk-0 prefetch: after nh=1's last chunk (p=1, Bcur=Bs1),
        // Bs0 is free; hide the gmem latency behind the X1 epilogue stores.
        if (nh == 1) ldb(W2c, DIM, 0, 0, Bs0);

        // epilogue: bias + relu, tf32-convert, store into X1 smem
        float2 bv[8];
#pragma unroll
        for (int ni = 0; ni < 8; ni++)
            bv[ni] = *reinterpret_cast<const float2*>(b1 + nh * 128 + wn * 64 + ni * 8 + 2 * t);

#pragma unroll
        for (int mi = 0; mi < 2; mi++)
#pragma unroll
            for (int half = 0; half < 2; half++) {
                const int row = wm * 32 + mi * 16 + g + half * 8;
                float* xp = X1 + (size_t)row * XST + nh * 128 + wn * 64 + 2 * t;
#pragma unroll
                for (int ni = 0; ni < 8; ni++) {
                    float x = fmaxf(acc[mi][ni][half * 2 + 0] + bv[ni].x, 0.0f);
                    float y = fmaxf(acc[mi][ni][half * 2 + 1] + bv[ni].y, 0.0f);
                    uint2 u; u.x = f2tf32(x); u.y = f2tf32(y);
                    *reinterpret_cast<uint2*>(xp + ni * 8) = u;
                }
            }
    }

    // ================= stage 2: Y = X1 @ W2 + b2 (K = 256) =================
#pragma unroll
    for (int mi = 0; mi < 2; mi++)
#pragma unroll
        for (int ni = 0; ni < 8; ni++)
#pragma unroll
            for (int r = 0; r < 4; r++) acc[mi][ni][r] = 0.0f;

    asm volatile("cp.async.wait_group 0;" ::: "memory");
    __syncthreads();                        // also makes X1 visible to all warps

#pragma unroll 1
    for (int kc = 0; kc < NK2; kc++) {
        const int p = kc & 1;
        float* Bcur = p ? Bs1 : Bs0;
        float* Bnxt = p ? Bs0 : Bs1;

        if (kc + 1 < NK2) ldb(W2c, DIM, kc + 1, 0, Bnxt);

#pragma unroll
        for (int kk = 0; kk < 4; kk++) {
            const int k0 = kc * 32 + kk * 8;
            uint32_t af[2][4];
#pragma unroll
            for (int mi = 0; mi < 2; mi++) {
                const float* ap = X1 + (size_t)(wm * 32 + mi * 16 + g) * XST + k0 + t;
                af[mi][0] = __float_as_uint(ap[0]);
                af[mi][1] = __float_as_uint(ap[8 * XST]);
                af[mi][2] = __float_as_uint(ap[4]);
                af[mi][3] = __float_as_uint(ap[8 * XST + 4]);
            }
#pragma unroll
            for (int ni = 0; ni < 8; ni++) {
                const float* bp = Bcur + (kk * 8 + t) * BST + wn * 64 + ni * 8 + g;
                uint32_t b0 = __float_as_uint(bp[0]);
                uint32_t b1r = __float_as_uint(bp[4 * BST]);
#pragma unroll
                for (int mi = 0; mi < 2; mi++) {
                    asm volatile(
                        "mma.sync.aligned.m16n8k8.row.col.f32.tf32.tf32.f32 "
                        "{%0,%1,%2,%3}, {%4,%5,%6,%7}, {%8,%9}, {%0,%1,%2,%3};"
                        : "+f"(acc[mi][ni][0]), "+f"(acc[mi][ni][1]),
                          "+f"(acc[mi][ni][2]), "+f"(acc[mi][ni][3])
                        : "r"(af[mi][0]), "r"(af[mi][1]), "r"(af[mi][2]), "r"(af[mi][3]),
                          "r"(b0), "r"(b1r));
                }
            }
        }

        if (kc + 1 < NK2)
            asm volatile("cp.async.wait_group 0;" ::: "memory");
        __syncthreads();
    }

    // ---- stage-2 epilogue ----
    float2 bv[8];
#pragma unroll
    for (int ni = 0; ni < 8; ni++)
        bv[ni] = *reinterpret_cast<const float2*>(b2 + wn * 64 + ni * 8 + 2 * t);

#pragma unroll
    for (int mi = 0; mi < 2; mi++)
#pragma unroll
        for (int half = 0; half < 2; half++) {
            const int row_l = wm * 32 + mi * 16 + g + half * 8;
            const int gm = m0 + row_l;
            if (gm < M) {
                const size_t orow = EDGE ? (size_t)dstIdx[row_l] : (size_t)gm;
                float* cp = Cout + orow * DIM + wn * 64 + 2 * t;
#pragma unroll
                for (int ni = 0; ni < 8; ni++) {
                    float x = acc[mi][ni][half * 2 + 0] + bv[ni].x;
                    float y = acc[mi][ni][half * 2 + 1] + bv[ni].y;
                    if (EDGE) {
                        asm volatile("red.global.add.v2.f32 [%0], {%1, %2};"
                                     :: "l"(cp + ni * 8), "f"(x), "f"(y) : "memory");
                    } else {
                        *reinterpret_cast<float2*>(cp + ni * 8) = make_float2(x, y);
                    }
                }
            }
        }
}

// ===================== launch =====================
extern "C" void kernel_launch(void* const* d_in, const int* in_sizes, int n_in,
                              void* d_out, int out_size)
{
    const float* H         = (const float*)d_in[0];
    const int*   edge_idx  = (const int*)  d_in[1];
    const float* edge_attr = (const float*)d_in[2];
    const float* eps       = (const float*)d_in[3];
    const float* msg_W1    = (const float*)d_in[4];
    const float* msg_b1    = (const float*)d_in[5];
    const float* msg_W2    = (const float*)d_in[6];
    const float* msg_b2    = (const float*)d_in[7];
    const float* self_W1   = (const float*)d_in[8];
    const float* self_b1   = (const float*)d_in[9];
    const float* self_W2   = (const float*)d_in[10];
    const float* self_b2   = (const float*)d_in[11];

    const int* src = edge_idx;
    const int* dst = edge_idx + N_EDGES;
    float* out = (float*)d_out;

    float *agg, *W1c, *W2c, *W3c, *W4c;
    cudaGetSymbolAddress((void**)&agg, g_agg);
    cudaGetSymbolAddress((void**)&W1c, g_W1c);
    cudaGetSymbolAddress((void**)&W2c, g_W2c);
    cudaGetSymbolAddress((void**)&W3c, g_W3c);
    cudaGetSymbolAddress((void**)&W4c, g_W4c);

    constexpr int K1 = DIM + EDGE_DIM;  // 192
    constexpr int SMEM = 1024 + 2 * (128 * 36 * 4) + 2 * (32 * 136 * 4)
                       + 128 * 260 * 4;  // 205824

    cudaFuncSetAttribute((const void*)fused_mlp<K1, true>,
                         cudaFuncAttributeMaxDynamicSharedMemorySize, SMEM);
    cudaFuncSetAttribute((const void*)fused_mlp<DIM, false>,
                         cudaFuncAttributeMaxDynamicSharedMemorySize, SMEM);

    // 0) agg = (1+eps)*H
    init_agg_kernel<<<cdiv(N_NODES * DIM, 256), 256>>>(H, eps);
    // 1) msg weights -> tf32 bits
    cvt2_tf32_kernel<<<cdiv(K1 * HID + HID * DIM, 256), 256>>>(
        msg_W1, W1c, K1 * HID, msg_W2, W2c, HID * DIM);
    // 2) self weights -> tf32 bits
    cvt2_tf32_kernel<<<cdiv(DIM * HID + HID * DIM, 256), 256>>>(
        self_W1, W3c, DIM * HID, self_W2, W4c, HID * DIM);

    // 3) fused edge MLP + scatter into agg   (ncu capture target: launch idx 3)
    fused_mlp<K1, true><<<cdiv(N_EDGES, 128), 256, SMEM>>>(
        nullptr, W1c, msg_b1, W2c, msg_b2, agg, src, dst, H, edge_attr, N_EDGES);

    // 4) fused node MLP -> out
    fused_mlp<DIM, false><<<cdiv(N_NODES, 128), 256, SMEM>>>(
        agg, W3c, self_b1, W4c, self_b2, out, nullptr, nullptr, nullptr, nullptr, N_NODES);
}

// round 8
// speedup vs baseline: 3.6709x; 1.1212x over previous
#include <cuda_runtime.h>
#include <cstdint>

// GINEdgeLayer, fused two-layer MLPs on legacy tf32 mma.sync (m16n8k8).
// out = MLP2((1+eps)*H + segment_sum(MLP1([H[src], edge_attr]), dst))
//
// R7: 512 threads / 16 warps per CTA (4x4 warp grid, 32x32 warp tile) to fix
// occupancy (was 8 warps/SM, tensor pipe 30%, issue 19%).
//
// Launch order (ncu capture lands on index 3 = fused edge kernel):
//   0: init_agg   1: cvt_msg   2: cvt_self   3: fused_edge   4: fused_node

static constexpr int N_NODES  = 20000;
static constexpr int N_EDGES  = 200000;
static constexpr int DIM      = 128;
static constexpr int EDGE_DIM = 64;
static constexpr int HID      = 256;

// ---- scratch (__device__ globals; no runtime allocation allowed) ----
__device__ float g_agg[(size_t)N_NODES * DIM];
__device__ __align__(16) float g_W1c[(DIM + EDGE_DIM) * HID];  // tf32 bits, layout preserved
__device__ __align__(16) float g_W2c[HID * DIM];
__device__ __align__(16) float g_W3c[DIM * HID];
__device__ __align__(16) float g_W4c[HID * DIM];

static inline int cdiv(int a, int b) { return (a + b - 1) / b; }

__device__ __forceinline__ uint32_t smem_u32(const void* p) {
    uint32_t a;
    asm("{ .reg .u64 t; cvta.to.shared.u64 t, %1; cvt.u32.u64 %0, t; }" : "=r"(a) : "l"(p));
    return a;
}
__device__ __forceinline__ uint32_t f2tf32(float f) {
    uint32_t r; asm("cvt.rna.tf32.f32 %0, %1;" : "=r"(r) : "f"(f)); return r;
}

__global__ __launch_bounds__(256)
void init_agg_kernel(const float* __restrict__ H, const float* __restrict__ eps) {
    int i = blockIdx.x * 256 + threadIdx.x;
    if (i < N_NODES * DIM) g_agg[i] = (1.0f + eps[0]) * H[i];
}

__global__ __launch_bounds__(256)
void cvt2_tf32_kernel(const float* __restrict__ Wa, float* __restrict__ WaC, int na,
                      const float* __restrict__ Wb, float* __restrict__ WbC, int nb) {
    int i = blockIdx.x * 256 + threadIdx.x;
    if (i < na)           WaC[i]      = __uint_as_float(f2tf32(Wa[i]));
    else if (i < na + nb) WbC[i - na] = __uint_as_float(f2tf32(Wb[i - na]));
}

// =====================================================================
// Fused 2-layer MLP, CTA tile = 128 rows, 512 threads (16 warps, 4M x 4N).
//   stage 1: X1 = relu(rowsA @ W1 + b1)   [128, 256] kept in SMEM (tf32 bits)
//   stage 2: Y  = X1 @ W2 + b2            [128, 128]
// EDGE: rowsA[m] = concat(H[src[m]], edge_attr[m]) (K1=192); Y scattered
//       via red.global.add into Cout[dst[m]].  !EDGE: rowsA = Ain (K1=128).
// =====================================================================
template<int K1, bool EDGE>
__global__ void __launch_bounds__(512, 1)
fused_mlp(const float* __restrict__ Ain,
          const float* __restrict__ W1c, const float* __restrict__ b1,
          const float* __restrict__ W2c, const float* __restrict__ b2,
          float*       __restrict__ Cout,
          const int*   __restrict__ srcv, const int* __restrict__ dstv,
          const float* __restrict__ H,   const float* __restrict__ EA,
          int M)
{
    constexpr int NK1 = K1 / 32;
    constexpr int NK2 = HID / 32;          // 8
    constexpr int AST = 36;                // A smem stride (floats)
    constexpr int BST = 136;               // B smem stride
    constexpr int XST = 260;               // X1 smem stride (conflict-free frags)
    constexpr int ABYTES = 128 * AST * 4;  // 18432
    constexpr int BBYTES = 32 * BST * 4;   // 17408
    constexpr int OFF_A  = 1024;
    constexpr int OFF_B  = OFF_A + 2 * ABYTES;            // 37888
    constexpr int OFF_X  = OFF_B + 2 * BBYTES;            // 72704
    // total = 72704 + 133120 = 205824
    static_assert((NK1 & 1) == 0, "stage-2 prefetch assumes even NK1 (Bs0 free)");

    extern __shared__ char smem[];
    int*   srcIdx = (int*)smem;
    int*   dstIdx = (int*)(smem + 512);
    float* As0 = (float*)(smem + OFF_A);
    float* As1 = (float*)(smem + OFF_A + ABYTES);
    float* Bs0 = (float*)(smem + OFF_B);
    float* Bs1 = (float*)(smem + OFF_B + BBYTES);
    float* X1  = (float*)(smem + OFF_X);

    const int tid  = threadIdx.x;
    const int wid  = tid >> 5, lane = tid & 31;
    const int g    = lane >> 2, t = lane & 3;
    const int wm   = wid & 3,  wn = wid >> 2;     // 4 x 4 warp grid
    const int m0   = blockIdx.x * 128;

    if (EDGE && tid < 128) {
        int gm = m0 + tid;
        int cm = gm < M ? gm : M - 1;
        srcIdx[tid] = srcv[cm];
        dstIdx[tid] = dstv[cm];
    }
    __syncthreads();

    // ---- stage-1 A staging: thread (row=tid/4, q=tid&3) handles 8 floats ----
    const int ar = tid >> 2, aq = tid & 3;
    int agm = m0 + ar; if (agm >= M) agm = M - 1;

    auto lda = [&](int kc, float4* v) {
        int k0 = kc * 32 + aq * 8;
        const float* s;
        if (EDGE) {
            s = (k0 < DIM) ? H + (size_t)srcIdx[ar] * DIM + k0
                           : EA + (size_t)agm * EDGE_DIM + (k0 - DIM);
        } else {
            s = Ain + (size_t)agm * K1 + k0;
        }
        v[0] = *reinterpret_cast<const float4*>(s);
        v[1] = *reinterpret_cast<const float4*>(s + 4);
    };
    auto sta = [&](float* buf, const float4* v) {
        float* d = buf + ar * AST + aq * 8;
#pragma unroll
        for (int j = 0; j < 2; j++) {
            uint4 u;
            u.x = f2tf32(v[j].x); u.y = f2tf32(v[j].y);
            u.z = f2tf32(v[j].z); u.w = f2tf32(v[j].w);
            *reinterpret_cast<uint4*>(d + j * 4) = u;
        }
    };

    // ---- B staging via cp.async: thread loads row bkr, 8 cols at bc0 ----
    const int bkr = tid >> 4;             // 0..31
    const int bc0 = (tid & 15) * 8;       // 0..120
    auto ldb = [&](const float* Bsrc, int ncols, int kc, int c0, float* buf) {
        uint32_t d = smem_u32(buf + bkr * BST + bc0);
        const float* s = Bsrc + (size_t)(kc * 32 + bkr) * ncols + c0 + bc0;
        asm volatile("cp.async.cg.shared.global [%0], [%1], 16;"
                     :: "r"(d), "l"(s) : "memory");
        asm volatile("cp.async.cg.shared.global [%0], [%1], 16;"
                     :: "r"(d + 16), "l"(s + 4) : "memory");
        asm volatile("cp.async.commit_group;" ::: "memory");
    };

    float acc[2][4][4];
    float4 av[2];

    // ================= stage 1: two N-halves of 128 =================
#pragma unroll 1
    for (int nh = 0; nh < 2; nh++) {
#pragma unroll
        for (int mi = 0; mi < 2; mi++)
#pragma unroll
            for (int ni = 0; ni < 4; ni++)
#pragma unroll
                for (int r = 0; r < 4; r++) acc[mi][ni][r] = 0.0f;

        ldb(W1c, HID, 0, nh * 128, Bs0);
        lda(0, av);
        sta(As0, av);
        asm volatile("cp.async.wait_group 0;" ::: "memory");
        __syncthreads();

#pragma unroll 1
        for (int kc = 0; kc < NK1; kc++) {
            const int p = kc & 1;
            float* Acur = p ? As1 : As0;
            float* Bcur = p ? Bs1 : Bs0;
            float* Anxt = p ? As0 : As1;
            float* Bnxt = p ? Bs0 : Bs1;

            if (kc + 1 < NK1) { ldb(W1c, HID, kc + 1, nh * 128, Bnxt); lda(kc + 1, av); }

#pragma unroll
            for (int kk = 0; kk < 4; kk++) {
                const int k0 = kk * 8;
                uint32_t af[2][4];
#pragma unroll
                for (int mi = 0; mi < 2; mi++) {
                    const float* ap = Acur + (wm * 32 + mi * 16 + g) * AST + k0 + t;
                    af[mi][0] = __float_as_uint(ap[0]);
                    af[mi][1] = __float_as_uint(ap[8 * AST]);
                    af[mi][2] = __float_as_uint(ap[4]);
                    af[mi][3] = __float_as_uint(ap[8 * AST + 4]);
                }
#pragma unroll
                for (int ni = 0; ni < 4; ni++) {
                    const float* bp = Bcur + (k0 + t) * BST + wn * 32 + ni * 8 + g;
                    uint32_t b0 = __float_as_uint(bp[0]);
                    uint32_t b1r = __float_as_uint(bp[4 * BST]);
#pragma unroll
                    for (int mi = 0; mi < 2; mi++) {
                        asm volatile(
                            "mma.sync.aligned.m16n8k8.row.col.f32.tf32.tf32.f32 "
                            "{%0,%1,%2,%3}, {%4,%5,%6,%7}, {%8,%9}, {%0,%1,%2,%3};"
                            : "+f"(acc[mi][ni][0]), "+f"(acc[mi][ni][1]),
                              "+f"(acc[mi][ni][2]), "+f"(acc[mi][ni][3])
                            : "r"(af[mi][0]), "r"(af[mi][1]), "r"(af[mi][2]), "r"(af[mi][3]),
                              "r"(b0), "r"(b1r));
                    }
                }
            }

            if (kc + 1 < NK1) {
                sta(Anxt, av);
                asm volatile("cp.async.wait_group 0;" ::: "memory");
            }
            __syncthreads();
        }

        // stage-2 chunk-0 prefetch into the free Bs0 (NK1 even -> last Bcur = Bs1)
        if (nh == 1) ldb(W2c, DIM, 0, 0, Bs0);

        // epilogue: bias + relu, tf32-convert, store into X1 smem
        float2 bv[4];
#pragma unroll
        for (int ni = 0; ni < 4; ni++)
            bv[ni] = *reinterpret_cast<const float2*>(b1 + nh * 128 + wn * 32 + ni * 8 + 2 * t);

#pragma unroll
        for (int mi = 0; mi < 2; mi++)
#pragma unroll
            for (int half = 0; half < 2; half++) {
                const int row = wm * 32 + mi * 16 + g + half * 8;
                float* xp = X1 + (size_t)row * XST + nh * 128 + wn * 32 + 2 * t;
#pragma unroll
                for (int ni = 0; ni < 4; ni++) {
                    float x = fmaxf(acc[mi][ni][half * 2 + 0] + bv[ni].x, 0.0f);
                    float y = fmaxf(acc[mi][ni][half * 2 + 1] + bv[ni].y, 0.0f);
                    uint2 u; u.x = f2tf32(x); u.y = f2tf32(y);
                    *reinterpret_cast<uint2*>(xp + ni * 8) = u;
                }
            }
    }

    // ================= stage 2: Y = X1 @ W2 + b2 (K = 256) =================
#pragma unroll
    for (int mi = 0; mi < 2; mi++)
#pragma unroll
        for (int ni = 0; ni < 4; ni++)
#pragma unroll
            for (int r = 0; r < 4; r++) acc[mi][ni][r] = 0.0f;

    asm volatile("cp.async.wait_group 0;" ::: "memory");
    __syncthreads();                        // also publishes X1 to all warps

#pragma unroll 1
    for (int kc = 0; kc < NK2; kc++) {
        const int p = kc & 1;
        float* Bcur = p ? Bs1 : Bs0;
        float* Bnxt = p ? Bs0 : Bs1;

        if (kc + 1 < NK2) ldb(W2c, DIM, kc + 1, 0, Bnxt);

#pragma unroll
        for (int kk = 0; kk < 4; kk++) {
            const int k0 = kc * 32 + kk * 8;
            uint32_t af[2][4];
#pragma unroll
            for (int mi = 0; mi < 2; mi++) {
                const float* ap = X1 + (size_t)(wm * 32 + mi * 16 + g) * XST + k0 + t;
                af[mi][0] = __float_as_uint(ap[0]);
                af[mi][1] = __float_as_uint(ap[8 * XST]);
                af[mi][2] = __float_as_uint(ap[4]);
                af[mi][3] = __float_as_uint(ap[8 * XST + 4]);
            }
#pragma unroll
            for (int ni = 0; ni < 4; ni++) {
                const float* bp = Bcur + (kk * 8 + t) * BST + wn * 32 + ni * 8 + g;
                uint32_t b0 = __float_as_uint(bp[0]);
                uint32_t b1r = __float_as_uint(bp[4 * BST]);
#pragma unroll
                for (int mi = 0; mi < 2; mi++) {
                    asm volatile(
                        "mma.sync.aligned.m16n8k8.row.col.f32.tf32.tf32.f32 "
                        "{%0,%1,%2,%3}, {%4,%5,%6,%7}, {%8,%9}, {%0,%1,%2,%3};"
                        : "+f"(acc[mi][ni][0]), "+f"(acc[mi][ni][1]),
                          "+f"(acc[mi][ni][2]), "+f"(acc[mi][ni][3])
                        : "r"(af[mi][0]), "r"(af[mi][1]), "r"(af[mi][2]), "r"(af[mi][3]),
                          "r"(b0), "r"(b1r));
                }
            }
        }

        if (kc + 1 < NK2)
            asm volatile("cp.async.wait_group 0;" ::: "memory");
        __syncthreads();
    }

    // ---- stage-2 epilogue ----
    float2 bv[4];
#pragma unroll
    for (int ni = 0; ni < 4; ni++)
        bv[ni] = *reinterpret_cast<const float2*>(b2 + wn * 32 + ni * 8 + 2 * t);

#pragma unroll
    for (int mi = 0; mi < 2; mi++)
#pragma unroll
        for (int half = 0; half < 2; half++) {
            const int row_l = wm * 32 + mi * 16 + g + half * 8;
            const int gm = m0 + row_l;
            if (gm < M) {
                const size_t orow = EDGE ? (size_t)dstIdx[row_l] : (size_t)gm;
                float* cp = Cout + orow * DIM + wn * 32 + 2 * t;
#pragma unroll
                for (int ni = 0; ni < 4; ni++) {
                    float x = acc[mi][ni][half * 2 + 0] + bv[ni].x;
                    float y = acc[mi][ni][half * 2 + 1] + bv[ni].y;
                    if (EDGE) {
                        asm volatile("red.global.add.v2.f32 [%0], {%1, %2};"
                                     :: "l"(cp + ni * 8), "f"(x), "f"(y) : "memory");
                    } else {
                        *reinterpret_cast<float2*>(cp + ni * 8) = make_float2(x, y);
                    }
                }
            }
        }
}

// ===================== launch =====================
extern "C" void kernel_launch(void* const* d_in, const int* in_sizes, int n_in,
                              void* d_out, int out_size)
{
    const float* H         = (const float*)d_in[0];
    const int*   edge_idx  = (const int*)  d_in[1];
    const float* edge_attr = (const float*)d_in[2];
    const float* eps       = (const float*)d_in[3];
    const float* msg_W1    = (const float*)d_in[4];
    const float* msg_b1    = (const float*)d_in[5];
    const float* msg_W2    = (const float*)d_in[6];
    const float* msg_b2    = (const float*)d_in[7];
    const float* self_W1   = (const float*)d_in[8];
    const float* self_b1   = (const float*)d_in[9];
    const float* self_W2   = (const float*)d_in[10];
    const float* self_b2   = (const float*)d_in[11];

    const int* src = edge_idx;
    const int* dst = edge_idx + N_EDGES;
    float* out = (float*)d_out;

    float *agg, *W1c, *W2c, *W3c, *W4c;
    cudaGetSymbolAddress((void**)&agg, g_agg);
    cudaGetSymbolAddress((void**)&W1c, g_W1c);
    cudaGetSymbolAddress((void**)&W2c, g_W2c);
    cudaGetSymbolAddress((void**)&W3c, g_W3c);
    cudaGetSymbolAddress((void**)&W4c, g_W4c);

    constexpr int K1 = DIM + EDGE_DIM;  // 192
    constexpr int SMEM = 1024 + 2 * (128 * 36 * 4) + 2 * (32 * 136 * 4)
                       + 128 * 260 * 4;  // 205824

    cudaFuncSetAttribute((const void*)fused_mlp<K1, true>,
                         cudaFuncAttributeMaxDynamicSharedMemorySize, SMEM);
    cudaFuncSetAttribute((const void*)fused_mlp<DIM, false>,
                         cudaFuncAttributeMaxDynamicSharedMemorySize, SMEM);

    // 0) agg = (1+eps)*H
    init_agg_kernel<<<cdiv(N_NODES * DIM, 256), 256>>>(H, eps);
    // 1) msg weights -> tf32 bits
    cvt2_tf32_kernel<<<cdiv(K1 * HID + HID * DIM, 256), 256>>>(
        msg_W1, W1c, K1 * HID, msg_W2, W2c, HID * DIM);
    // 2) self weights -> tf32 bits
    cvt2_tf32_kernel<<<cdiv(DIM * HID + HID * DIM, 256), 256>>>(
        self_W1, W3c, DIM * HID, self_W2, W4c, HID * DIM);

    // 3) fused edge MLP + scatter into agg   (ncu capture target: launch idx 3)
    fused_mlp<K1, true><<<cdiv(N_EDGES, 128), 512, SMEM>>>(
        nullptr, W1c, msg_b1, W2c, msg_b2, agg, src, dst, H, edge_attr, N_EDGES);

    // 4) fused node MLP -> out
    fused_mlp<DIM, false><<<cdiv(N_NODES, 128), 512, SMEM>>>(
        agg, W3c, self_b1, W4c, self_b2, out, nullptr, nullptr, nullptr, nullptr, N_NODES);
}

// round 9
// speedup vs baseline: 3.7967x; 1.0343x over previous
#include <cuda_runtime.h>
#include <cstdint>

// GINEdgeLayer, fused two-layer MLPs on legacy tf32 mma.sync (m16n8k8).
// out = MLP2((1+eps)*H + segment_sum(MLP1([H[src], edge_attr]), dst))
//
// R8: k-permuted operand layouts -> all fragment feeds become LDS.128.
//   pos(w) = (w&3)*8 + ((w>>3)&3)*2 + ((w>>2)&1)   (bijection on 0..31)
// Weights are pre-permuted to [chunk][col][36] in the cvt kernels, so B
// staging is a flat cp.async copy. A is staged with permuted STS.64; X1 is
// written permuted (scalar STS) and read with LDS.128 in stage 2.
//
// Launch order (ncu capture = index 3 = fused edge kernel):
//   0: init_agg   1: cvt_msg   2: cvt_self   3: fused_edge   4: fused_node

static constexpr int N_NODES  = 20000;
static constexpr int N_EDGES  = 200000;
static constexpr int DIM      = 128;
static constexpr int EDGE_DIM = 64;
static constexpr int HID      = 256;

// ---- scratch (__device__ globals; no runtime allocation allowed) ----
__device__ float g_agg[(size_t)N_NODES * DIM];
__device__ __align__(16) float g_W1p[2 * 6 * 128 * 36];  // [nh][kc][col][36] tf32
__device__ __align__(16) float g_W2p[8 * 128 * 36];      // [kc][col][36]
__device__ __align__(16) float g_W3p[2 * 4 * 128 * 36];  // [nh][kc][col][36]
__device__ __align__(16) float g_W4p[8 * 128 * 36];      // [kc][col][36]

static inline int cdiv(int a, int b) { return (a + b - 1) / b; }

__device__ __forceinline__ uint32_t smem_u32(const void* p) {
    uint32_t a;
    asm("{ .reg .u64 t; cvta.to.shared.u64 t, %1; cvt.u32.u64 %0, t; }" : "=r"(a) : "l"(p));
    return a;
}
__device__ __forceinline__ uint32_t f2tf32(float f) {
    uint32_t r; asm("cvt.rna.tf32.f32 %0, %1;" : "=r"(r) : "f"(f)); return r;
}
__device__ __forceinline__ int kperm(int w) {        // w in [0,32)
    return (w & 3) * 8 + ((w >> 3) & 3) * 2 + ((w >> 2) & 1);
}

__global__ __launch_bounds__(256)
void init_agg_kernel(const float* __restrict__ H, const float* __restrict__ eps) {
    int i = blockIdx.x * 256 + threadIdx.x;
    if (i < N_NODES * DIM) g_agg[i] = (1.0f + eps[0]) * H[i];
}

// W[K,N] row-major -> P[(chunk*128 + col)*36 + pos], chunk = (n>>7)*(K/32) + (k>>5)
__device__ __forceinline__ void perm_write(const float* __restrict__ W,
                                           float* __restrict__ P,
                                           int K, int N, int idx) {
    int k = idx / N, n = idx - k * N;
    int chunk = (n >> 7) * (K >> 5) + (k >> 5);
    int col = n & 127;
    int pos = kperm(k & 31);
    P[(size_t)(chunk * 128 + col) * 36 + pos] = __uint_as_float(f2tf32(W[idx]));
}

__global__ __launch_bounds__(256)
void cvt_perm2_kernel(const float* __restrict__ Wa, float* __restrict__ Pa, int Ka, int Na,
                      const float* __restrict__ Wb, float* __restrict__ Pb, int Kb, int Nb) {
    int i = blockIdx.x * 256 + threadIdx.x;
    int na = Ka * Na;
    if (i < na)                perm_write(Wa, Pa, Ka, Na, i);
    else if (i < na + Kb * Nb) perm_write(Wb, Pb, Kb, Nb, i - na);
}

// =====================================================================
// Fused 2-layer MLP, CTA tile = 128 rows, 512 threads (16 warps, 4M x 4N).
//   stage 1: X1 = relu(rowsA @ W1 + b1)   [128, 256] in SMEM (tf32, permuted)
//   stage 2: Y  = X1 @ W2 + b2            [128, 128]
// EDGE: rowsA[m] = concat(H[src[m]], edge_attr[m]) (K1=192); Y scattered
//       via red.global.add into Cout[dst[m]].  !EDGE: rowsA = Ain (K1=128).
// =====================================================================
template<int K1, bool EDGE>
__global__ void __launch_bounds__(512, 1)
fused_mlp(const float* __restrict__ Ain,
          const float* __restrict__ W1p, const float* __restrict__ b1,
          const float* __restrict__ W2p, const float* __restrict__ b2,
          float*       __restrict__ Cout,
          const int*   __restrict__ srcv, const int* __restrict__ dstv,
          const float* __restrict__ H,   const float* __restrict__ EA,
          int M)
{
    constexpr int NK1 = K1 / 32;
    constexpr int NK2 = HID / 32;           // 8
    constexpr int AST = 36;                 // A smem row stride (floats)
    constexpr int BST = 36;                 // B smem col stride (floats)
    constexpr int XST = 260;                // X1 row stride (260 % 32 == 4)
    constexpr int ABYTES = 128 * AST * 4;   // 18432
    constexpr int BBYTES = 128 * BST * 4;   // 18432
    constexpr int BCHUNK16 = BBYTES / 16;   // 1152 16-byte chunks
    constexpr int OFF_A = 1024;
    constexpr int OFF_B = OFF_A + 2 * ABYTES;     // 37888
    constexpr int OFF_X = OFF_B + 2 * BBYTES;     // 74752
    // total = 74752 + 128*260*4 = 207872
    static_assert((NK1 & 1) == 0, "stage-2 prefetch assumes even NK1");

    extern __shared__ char smem[];
    int*   srcIdx = (int*)smem;
    int*   dstIdx = (int*)(smem + 512);
    float* As0 = (float*)(smem + OFF_A);
    float* As1 = (float*)(smem + OFF_A + ABYTES);
    float* Bs0 = (float*)(smem + OFF_B);
    float* Bs1 = (float*)(smem + OFF_B + BBYTES);
    float* X1  = (float*)(smem + OFF_X);

    const int tid  = threadIdx.x;
    const int wid  = tid >> 5, lane = tid & 31;
    const int g    = lane >> 2, t = lane & 3;
    const int wm   = wid & 3,  wn = wid >> 2;     // 4 x 4 warp grid
    const int m0   = blockIdx.x * 128;

    if (EDGE && tid < 128) {
        int gm = m0 + tid;
        int cm = gm < M ? gm : M - 1;
        srcIdx[tid] = srcv[cm];
        dstIdx[tid] = dstv[cm];
    }
    __syncthreads();

    // ---- A staging: thread (row=tid/4, aq=tid&3) handles 8 consecutive k ----
    const int ar = tid >> 2, aq = tid & 3;
    int agm = m0 + ar; if (agm >= M) agm = M - 1;

    auto lda = [&](int kc, float4* v) {
        int k0 = kc * 32 + aq * 8;
        const float* s;
        if (EDGE) {
            s = (k0 < DIM) ? H + (size_t)srcIdx[ar] * DIM + k0
                           : EA + (size_t)agm * EDGE_DIM + (k0 - DIM);
        } else {
            s = Ain + (size_t)agm * K1 + k0;
        }
        v[0] = *reinterpret_cast<const float4*>(s);
        v[1] = *reinterpret_cast<const float4*>(s + 4);
    };
    // permuted store: pairs (j, j+4) land at adjacent pos -> STS.64
    auto sta = [&](float* buf, const float4* v) {
        const float f[8] = { v[0].x, v[0].y, v[0].z, v[0].w,
                             v[1].x, v[1].y, v[1].z, v[1].w };
        float* d = buf + ar * AST + aq * 2;
#pragma unroll
        for (int j = 0; j < 4; j++) {
            uint2 u; u.x = f2tf32(f[j]); u.y = f2tf32(f[j + 4]);
            *reinterpret_cast<uint2*>(d + j * 8) = u;
        }
    };

    // ---- B staging: flat cp.async copy of one pre-permuted 18432-B chunk ----
    auto ldb = [&](const float* srcChunk, float* buf) {
        uint32_t d = smem_u32(buf);
        const char* s = (const char*)srcChunk;
#pragma unroll
        for (int i = 0; i < 3; i++) {
            int idx = tid + i * 512;
            if (idx < BCHUNK16)
                asm volatile("cp.async.cg.shared.global [%0], [%1], 16;"
                             :: "r"(d + idx * 16), "l"(s + (size_t)idx * 16) : "memory");
        }
        asm volatile("cp.async.commit_group;" ::: "memory");
    };

    float acc[2][4][4];
    float4 av[2];

    // fragment compute core: A from abase (stride ast), B from Bcur
    auto mma_chunk = [&](const float* abase, int ast, const float* Bcur) {
        float a[2][2][8];                         // [mi][lo/hi][8]
#pragma unroll
        for (int mi = 0; mi < 2; mi++)
#pragma unroll
            for (int lh = 0; lh < 2; lh++) {
                const float* ap = abase + (mi * 16 + lh * 8) * ast;
                *reinterpret_cast<float4*>(&a[mi][lh][0]) =
                    *reinterpret_cast<const float4*>(ap);
                *reinterpret_cast<float4*>(&a[mi][lh][4]) =
                    *reinterpret_cast<const float4*>(ap + 4);
            }
#pragma unroll
        for (int ni = 0; ni < 4; ni++) {
            const float* bp = Bcur + (wn * 32 + ni * 8 + g) * BST + t * 8;
            float b[8];
            *reinterpret_cast<float4*>(&b[0]) = *reinterpret_cast<const float4*>(bp);
            *reinterpret_cast<float4*>(&b[4]) = *reinterpret_cast<const float4*>(bp + 4);
#pragma unroll
            for (int kk = 0; kk < 4; kk++) {
                uint32_t b0 = __float_as_uint(b[2 * kk]);
                uint32_t b1 = __float_as_uint(b[2 * kk + 1]);
#pragma unroll
                for (int mi = 0; mi < 2; mi++) {
                    asm volatile(
                        "mma.sync.aligned.m16n8k8.row.col.f32.tf32.tf32.f32 "
                        "{%0,%1,%2,%3}, {%4,%5,%6,%7}, {%8,%9}, {%0,%1,%2,%3};"
                        : "+f"(acc[mi][ni][0]), "+f"(acc[mi][ni][1]),
                          "+f"(acc[mi][ni][2]), "+f"(acc[mi][ni][3])
                        : "r"(__float_as_uint(a[mi][0][2 * kk])),
                          "r"(__float_as_uint(a[mi][1][2 * kk])),
                          "r"(__float_as_uint(a[mi][0][2 * kk + 1])),
                          "r"(__float_as_uint(a[mi][1][2 * kk + 1])),
                          "r"(b0), "r"(b1));
                }
            }
        }
    };

    // ================= stage 1: two N-halves of 128 =================
#pragma unroll 1
    for (int nh = 0; nh < 2; nh++) {
#pragma unroll
        for (int mi = 0; mi < 2; mi++)
#pragma unroll
            for (int ni = 0; ni < 4; ni++)
#pragma unroll
                for (int r = 0; r < 4; r++) acc[mi][ni][r] = 0.0f;

        ldb(W1p + (size_t)(nh * NK1) * 128 * 36, Bs0);
        lda(0, av);
        sta(As0, av);
        asm volatile("cp.async.wait_group 0;" ::: "memory");
        __syncthreads();

#pragma unroll 1
        for (int kc = 0; kc < NK1; kc++) {
            const int p = kc & 1;
            float* Acur = p ? As1 : As0;
            float* Bcur = p ? Bs1 : Bs0;
            float* Anxt = p ? As0 : As1;
            float* Bnxt = p ? Bs0 : Bs1;

            if (kc + 1 < NK1) {
                ldb(W1p + (size_t)(nh * NK1 + kc + 1) * 128 * 36, Bnxt);
                lda(kc + 1, av);
            }

            mma_chunk(Acur + (wm * 32 + g) * AST + t * 8, AST, Bcur);

            if (kc + 1 < NK1) {
                sta(Anxt, av);
                asm volatile("cp.async.wait_group 0;" ::: "memory");
            }
            __syncthreads();
        }

        // stage-2 chunk-0 prefetch into the free Bs0 (NK1 even -> last Bcur = Bs1)
        if (nh == 1) ldb(W2p, Bs0);

        // epilogue: bias + relu, tf32-convert, permuted store into X1 smem
        float2 bv[4];
#pragma unroll
        for (int ni = 0; ni < 4; ni++)
            bv[ni] = *reinterpret_cast<const float2*>(b1 + nh * 128 + wn * 32 + ni * 8 + 2 * t);

        const int t2 = 2 * t, t3 = 2 * t + 1;
        const int posx = (t2 & 3) * 8 + (t2 >> 2);   // + ni*2
        const int posy = (t3 & 3) * 8 + (t3 >> 2);
#pragma unroll
        for (int mi = 0; mi < 2; mi++)
#pragma unroll
            for (int half = 0; half < 2; half++) {
                const int row = wm * 32 + mi * 16 + g + half * 8;
                float* xp = X1 + (size_t)row * XST + (nh * 4 + wn) * 32;
#pragma unroll
                for (int ni = 0; ni < 4; ni++) {
                    float x = fmaxf(acc[mi][ni][half * 2 + 0] + bv[ni].x, 0.0f);
                    float y = fmaxf(acc[mi][ni][half * 2 + 1] + bv[ni].y, 0.0f);
                    xp[posx + ni * 2] = __uint_as_float(f2tf32(x));
                    xp[posy + ni * 2] = __uint_as_float(f2tf32(y));
                }
            }
    }

    // ================= stage 2: Y = X1 @ W2 + b2 (K = 256) =================
#pragma unroll
    for (int mi = 0; mi < 2; mi++)
#pragma unroll
        for (int ni = 0; ni < 4; ni++)
#pragma unroll
            for (int r = 0; r < 4; r++) acc[mi][ni][r] = 0.0f;

    asm volatile("cp.async.wait_group 0;" ::: "memory");
    __syncthreads();                        // publishes X1 to all warps

#pragma unroll 1
    for (int kc = 0; kc < NK2; kc++) {
        const int p = kc & 1;
        float* Bcur = p ? Bs1 : Bs0;
        float* Bnxt = p ? Bs0 : Bs1;

        if (kc + 1 < NK2) ldb(W2p + (size_t)(kc + 1) * 128 * 36, Bnxt);

        mma_chunk(X1 + (size_t)(wm * 32 + g) * XST + kc * 32 + t * 8, XST, Bcur);

        if (kc + 1 < NK2)
            asm volatile("cp.async.wait_group 0;" ::: "memory");
        __syncthreads();
    }

    // ---- stage-2 epilogue ----
    float2 bv[4];
#pragma unroll
    for (int ni = 0; ni < 4; ni++)
        bv[ni] = *reinterpret_cast<const float2*>(b2 + wn * 32 + ni * 8 + 2 * t);

#pragma unroll
    for (int mi = 0; mi < 2; mi++)
#pragma unroll
        for (int half = 0; half < 2; half++) {
            const int row_l = wm * 32 + mi * 16 + g + half * 8;
            const int gm = m0 + row_l;
            if (gm < M) {
                const size_t orow = EDGE ? (size_t)dstIdx[row_l] : (size_t)gm;
                float* cp = Cout + orow * DIM + wn * 32 + 2 * t;
#pragma unroll
                for (int ni = 0; ni < 4; ni++) {
                    float x = acc[mi][ni][half * 2 + 0] + bv[ni].x;
                    float y = acc[mi][ni][half * 2 + 1] + bv[ni].y;
                    if (EDGE) {
                        asm volatile("red.global.add.v2.f32 [%0], {%1, %2};"
                                     :: "l"(cp + ni * 8), "f"(x), "f"(y) : "memory");
                    } else {
                        *reinterpret_cast<float2*>(cp + ni * 8) = make_float2(x, y);
                    }
                }
            }
        }
}

// ===================== launch =====================
extern "C" void kernel_launch(void* const* d_in, const int* in_sizes, int n_in,
                              void* d_out, int out_size)
{
    const float* H         = (const float*)d_in[0];
    const int*   edge_idx  = (const int*)  d_in[1];
    const float* edge_attr = (const float*)d_in[2];
    const float* eps       = (const float*)d_in[3];
    const float* msg_W1    = (const float*)d_in[4];
    const float* msg_b1    = (const float*)d_in[5];
    const float* msg_W2    = (const float*)d_in[6];
    const float* msg_b2    = (const float*)d_in[7];
    const float* self_W1   = (const float*)d_in[8];
    const float* self_b1   = (const float*)d_in[9];
    const float* self_W2   = (const float*)d_in[10];
    const float* self_b2   = (const float*)d_in[11];

    const int* src = edge_idx;
    const int* dst = edge_idx + N_EDGES;
    float* out = (float*)d_out;

    float *agg, *W1p, *W2p, *W3p, *W4p;
    cudaGetSymbolAddress((void**)&agg, g_agg);
    cudaGetSymbolAddress((void**)&W1p, g_W1p);
    cudaGetSymbolAddress((void**)&W2p, g_W2p);
    cudaGetSymbolAddress((void**)&W3p, g_W3p);
    cudaGetSymbolAddress((void**)&W4p, g_W4p);

    constexpr int K1 = DIM + EDGE_DIM;  // 192
    constexpr int SMEM = 1024 + 2 * (128 * 36 * 4) + 2 * (128 * 36 * 4)
                       + 128 * 260 * 4;  // 207872

    cudaFuncSetAttribute((const void*)fused_mlp<K1, true>,
                         cudaFuncAttributeMaxDynamicSharedMemorySize, SMEM);
    cudaFuncSetAttribute((const void*)fused_mlp<DIM, false>,
                         cudaFuncAttributeMaxDynamicSharedMemorySize, SMEM);

    // 0) agg = (1+eps)*H
    init_agg_kernel<<<cdiv(N_NODES * DIM, 256), 256>>>(H, eps);
    // 1) msg weights -> permuted tf32
    cvt_perm2_kernel<<<cdiv(K1 * HID + HID * DIM, 256), 256>>>(
        msg_W1, W1p, K1, HID, msg_W2, W2p, HID, DIM);
    // 2) self weights -> permuted tf32
    cvt_perm2_kernel<<<cdiv(DIM * HID + HID * DIM, 256), 256>>>(
        self_W1, W3p, DIM, HID, self_W2, W4p, HID, DIM);

    // 3) fused edge MLP + scatter into agg   (ncu capture target: launch idx 3)
    fused_mlp<K1, true><<<cdiv(N_EDGES, 128), 512, SMEM>>>(
        nullptr, W1p, msg_b1, W2p, msg_b2, agg, src, dst, H, edge_attr, N_EDGES);

    // 4) fused node MLP -> out
    fused_mlp<DIM, false><<<cdiv(N_NODES, 128), 512, SMEM>>>(
        agg, W3p, self_b1, W4p, self_b2, out, nullptr, nullptr, nullptr, nullptr, N_NODES);
}